// round 8
// baseline (speedup 1.0000x reference)
#include <cuda_runtime.h>
#include <cuda_bf16.h>

#define S 128

__device__ __align__(16) unsigned g_mrow[16 * S * 4];  // bit j: mask[b,i,j]
__device__ __align__(16) unsigned g_span[16 * S * 4];  // bit k: mask[b,j,k] | mask[b,k,j]

__device__ __forceinline__ float sigmoidf_(float x) {
    return 1.0f / (1.0f + __expf(-x));
}
__device__ __forceinline__ unsigned pick_word(uint4 v, int wd) {
    return (wd == 0) ? v.x : (wd == 1) ? v.y : (wd == 2) ? v.z : v.w;
}

// ---- Pre-kernel: pack masks to bits, one CTA per batch ----
__global__ __launch_bounds__(512)
void mask_pack_kernel(const int* __restrict__ mask) {
    __shared__ unsigned char m[S * 132];
    const int b = blockIdx.x;
    const int t = threadIdx.x;
    const int4* mg = reinterpret_cast<const int4*>(mask + (size_t)b * S * S);
    #pragma unroll
    for (int n = 0; n < 8; n++) {
        int idx = n * 512 + t;
        int row = idx >> 5, c4 = idx & 31;
        int4 v = __ldg(mg + idx);
        uchar4 u;
        u.x = (unsigned char)(v.x != 0); u.y = (unsigned char)(v.y != 0);
        u.z = (unsigned char)(v.z != 0); u.w = (unsigned char)(v.w != 0);
        *reinterpret_cast<uchar4*>(&m[row * 132 + (c4 << 2)]) = u;
    }
    __syncthreads();
    const int w = t >> 5, lane = t & 31;
    for (int task = w; task < 512; task += 16) {
        const int j  = task >> 2;
        const int wd = task & 3;
        const int k  = (wd << 5) + lane;
        unsigned mjk = m[j * 132 + k];
        unsigned mkj = m[k * 132 + j];
        unsigned rw = __ballot_sync(0xffffffffu, mjk != 0);
        unsigned sw = __ballot_sync(0xffffffffu, (mjk | mkj) != 0);
        if (lane == 0) {
            g_mrow[(b * S + j) * 4 + wd] = rw;
            g_span[(b * S + j) * 4 + wd] = sw;
        }
    }
}

// ---- Main: one CTA per (b,i), 256 threads, M direct to registers, shuffle reduce ----
__global__ __launch_bounds__(256, 2)
void mfvi_main(const float* __restrict__ s_span,
               const float* __restrict__ s_pair,
               float* __restrict__ out)
{
    __shared__ __align__(16) float pbuf[2][S];   // double-buffered sigmoid(q)

    const int t    = threadIdx.x;
    const int lane = t & 31;
    const int w    = t >> 5;        // warp 0..7
    const int g    = lane >> 3;     // row subgroup 0..3
    const int c    = lane & 7;      // k-chunk lane 0..7

    const int n = blockIdx.x;
    const int b = n >> 7;
    const int i = n & 127;

    const uint4 mr = *reinterpret_cast<const uint4*>(&g_mrow[(b * S + i) * 4]);

    // ---- Load + mask M strips straight into registers (coalesced LDG.128) ----
    // rows j(rr) = w*16 + rr*4 + g ; k(qq,e) = qq*32 + c*4 + e
    float M[64];
    float ss[4];
    int   jr[4];
    #pragma unroll
    for (int rr = 0; rr < 4; rr++) {
        const int j = (w << 4) + (rr << 2) + g;
        jr[rr] = j;
        ss[rr] = __ldg(&s_span[(size_t)n * S + j]);     // broadcast-ish per 8 lanes
        const bool live = (pick_word(mr, j >> 5) >> (j & 31)) & 1u;
        uint4 sp = make_uint4(0u, 0u, 0u, 0u);
        if (live) sp = *reinterpret_cast<const uint4*>(&g_span[(b * S + j) * 4]);
        const int lo = min(i, j), hi = max(i, j);
        const float* rowp = s_pair + ((size_t)n * S + (size_t)j) * S;
        #pragma unroll
        for (int qq = 0; qq < 4; qq++) {
            float4 v = make_float4(0.f, 0.f, 0.f, 0.f);
            if (live)
                v = __ldg(reinterpret_cast<const float4*>(rowp + (qq << 5)) + c);
            unsigned nib = (pick_word(sp, qq) >> (c << 2)) & 0xFu;
            if ((lo >> 5) == qq && ((lo & 31) >> 2) == c) nib &= ~(1u << (lo & 3));
            if ((hi >> 5) == qq && ((hi & 31) >> 2) == c) nib &= ~(1u << (hi & 3));
            const int base = rr * 16 + qq * 4;
            M[base + 0] = (nib & 1u) ? v.x : 0.f;
            M[base + 1] = (nib & 2u) ? v.y : 0.f;
            M[base + 2] = (nib & 4u) ? v.z : 0.f;
            M[base + 3] = (nib & 8u) ? v.w : 0.f;
        }
    }

    // ---- p0 init ----
    if (t < S) pbuf[0][t] = sigmoidf_(__ldg(&s_span[(size_t)n * S + t]));
    __syncthreads();

    // ---- 3 MFVI iterations: 1 barrier each (double-buffered p) ----
    #pragma unroll
    for (int it = 0; it < 3; it++) {
        const float* pr = pbuf[it & 1];
        // this thread's 16 p values (4 LDS.128, ~128B unique per warp)
        float4 pv[4];
        #pragma unroll
        for (int qq = 0; qq < 4; qq++)
            pv[qq] = *reinterpret_cast<const float4*>(&pr[(qq << 5) + (c << 2)]);

        float acc[4];
        #pragma unroll
        for (int rr = 0; rr < 4; rr++) {
            float a0 = 0.f, a1 = 0.f, a2 = 0.f, a3 = 0.f;
            #pragma unroll
            for (int qq = 0; qq < 4; qq++) {
                const int base = rr * 16 + qq * 4;
                a0 = fmaf(pv[qq].x, M[base + 0], a0);
                a1 = fmaf(pv[qq].y, M[base + 1], a1);
                a2 = fmaf(pv[qq].z, M[base + 2], a2);
                a3 = fmaf(pv[qq].w, M[base + 3], a3);
            }
            acc[rr] = (a0 + a1) + (a2 + a3);
        }
        // butterfly over the 8 k-chunk lanes (stays within each g-group)
        #pragma unroll
        for (int rr = 0; rr < 4; rr++) {
            float s = acc[rr];
            s += __shfl_xor_sync(0xffffffffu, s, 1);
            s += __shfl_xor_sync(0xffffffffu, s, 2);
            s += __shfl_xor_sync(0xffffffffu, s, 4);
            acc[rr] = s;
        }
        if (it < 2) {
            if (c == 0) {
                #pragma unroll
                for (int rr = 0; rr < 4; rr++)
                    pbuf[(it & 1) ^ 1][jr[rr]] = sigmoidf_(ss[rr] + acc[rr]);
            }
            __syncthreads();
        } else {
            if (c == 0) {
                #pragma unroll
                for (int rr = 0; rr < 4; rr++)
                    out[(size_t)n * S + jr[rr]] = sigmoidf_(ss[rr] + acc[rr]);
            }
        }
    }
}

extern "C" void kernel_launch(void* const* d_in, const int* in_sizes, int n_in,
                              void* d_out, int out_size) {
    const float* s_span = (const float*)d_in[0];
    const float* s_pair = (const float*)d_in[1];
    const int*   mask   = (const int*)d_in[2];
    float* out = (float*)d_out;

    mask_pack_kernel<<<16, 512>>>(mask);
    mfvi_main<<<16 * 128, 256>>>(s_span, s_pair, out);
}